// round 8
// baseline (speedup 1.0000x reference)
#include <cuda_runtime.h>
#include <cstdint>

// ============================================================================
// KLinear: y = x @ W + bias,  W = (kron(L0,R0)+kron(L1,R1)+kron(L2,R2))/3
// Factorized two-stage GEMMs on legacy tensor cores (mma.sync m16n8k8 tf32,
// base ISA — tcgen05 unavailable: harness targets sm_103, not sm_103a).
//   GEMM1: T[(m,a), d] = sum_c x[m, a*C+c] * R[c,d]      (M=4A, N=D, K=C)
//   GEMM2: y[m][b*D+d] += sum_a (L[a,b]/3) * T[(m,a), d]  (per m: M=B, N=D, K=A)
// CTA = 4 rows of x, 512 threads / 16 warps, 8 m16n8 tiles per warp per GEMM.
// y accumulated in swizzled smem across factors; bias added at epilogue.
// R6 bug fixed: y row stride must cover n + 2*(n>>5) -> YS = 4352 (was 4224).
// ============================================================================

static constexpr int THREADS = 512;
static constexpr int MT = 4;
static constexpr int NF = 4096;

// SMEM layout (float indices)
static constexpr int YS    = 4352;            // y row stride: 4096 + 2*(4096/32)
static constexpr int OFF_Y = 0;               // 4 * 4352          = 17408
static constexpr int OFF_T = 17408;           // up to 512*40      = 20480
static constexpr int OFF_X = 37888;           // up to 512*20      = 10240 (aliased by LT)
static constexpr int OFF_R = 48128;           // up to 16*136      = 2176
static constexpr int SMEM_FLOATS = 50304;
static constexpr int SMEM_BYTES  = SMEM_FLOATS * 4;   // 201216 B

__device__ __forceinline__ uint32_t f2tf(float f) {
    uint32_t r; asm("cvt.rna.tf32.f32 %0, %1;" : "=r"(r) : "f"(f)); return r;
}

__device__ __forceinline__ void mma8(float* c, const uint32_t* a, const uint32_t* b) {
    asm volatile(
        "mma.sync.aligned.m16n8k8.row.col.f32.tf32.tf32.f32 "
        "{%0,%1,%2,%3}, {%4,%5,%6,%7}, {%8,%9}, {%0,%1,%2,%3};"
        : "+f"(c[0]), "+f"(c[1]), "+f"(c[2]), "+f"(c[3])
        : "r"(a[0]), "r"(a[1]), "r"(a[2]), "r"(a[3]), "r"(b[0]), "r"(b[1]));
}

template<int A, int B, int C, int D>
__device__ __forceinline__ void factor(
    const float* __restrict__ x, const float* __restrict__ Lg,
    const float* __restrict__ Rg, float* __restrict__ smem, int m0, int tid)
{
    constexpr int DP  = D + 8;          // padded row stride (R, T): conflict-free frags
    constexpr int XS  = 20;             // x chunk row stride (16 + 4)
    constexpr int LTS = 36;             // LT chunk row stride (32 + 4)
    constexpr int NC1 = C / 16;         // K chunks, stage 1
    constexpr int NC2 = A / 32;         // K chunks, stage 2
    constexpr int TC1 = D / 8;          // GEMM1 tile grid: (4A/16) x (D/8) = 128
    constexpr int WC1 = TC1 / 4;        // warp grid cols (warp block = 2x4 tiles)
    constexpr int TC2 = D / 8;          // GEMM2 per-m grid: (B/16) x (D/8) = 32
    constexpr int WC2 = (TC2 >= 4) ? ((TC2 / 4 <= 4) ? TC2 / 4 : 4) : 1;

    float*    ys  = smem + OFF_Y;
    uint32_t* ts  = (uint32_t*)(smem + OFF_T);
    uint32_t* xs  = (uint32_t*)(smem + OFF_X);
    uint32_t* rs  = (uint32_t*)(smem + OFF_R);
    uint32_t* lts = (uint32_t*)(smem + OFF_X);   // alias (x chunk dead in stage 2)

    const int w    = tid >> 5;
    const int lane = tid & 31;
    const int gid  = lane >> 2;     // groupID
    const int tig  = lane & 3;      // thread-in-group

    // ================= GEMM1 =================
    const int wr1 = w / WC1, wc1 = w % WC1;
    float accT[2][4][4];
    #pragma unroll
    for (int i = 0; i < 2; i++)
        #pragma unroll
        for (int j = 0; j < 4; j++)
            #pragma unroll
            for (int q = 0; q < 4; q++) accT[i][j][q] = 0.0f;

    for (int ck = 0; ck < NC1; ck++) {
        __syncthreads();   // prev chunk consumed / prev factor fully done

        // ---- x chunk: [4A rows][16 c], tf32, stride 20 ----
        #pragma unroll
        for (int i4 = tid; i4 < 4 * A * 4; i4 += THREADS) {
            int r = i4 >> 2, c4 = i4 & 3;
            int m = r / A, a = r % A;
            float4 v = *(const float4*)&x[(size_t)(m0 + m) * NF + a * C + ck * 16 + c4 * 4];
            uint4 u = make_uint4(f2tf(v.x), f2tf(v.y), f2tf(v.z), f2tf(v.w));
            *(uint4*)&xs[r * XS + c4 * 4] = u;
        }
        // ---- R chunk: [16 c][D], tf32, stride DP ----
        #pragma unroll
        for (int i4 = tid; i4 < 16 * (D / 4); i4 += THREADS) {
            int k = i4 / (D / 4), d4 = i4 % (D / 4);
            float4 v = *(const float4*)&Rg[(ck * 16 + k) * D + d4 * 4];
            uint4 u = make_uint4(f2tf(v.x), f2tf(v.y), f2tf(v.z), f2tf(v.w));
            *(uint4*)&rs[k * DP + d4 * 4] = u;
        }
        __syncthreads();

        #pragma unroll
        for (int kt = 0; kt < 2; kt++) {
            uint32_t af[2][4], bf[4][2];
            #pragma unroll
            for (int i = 0; i < 2; i++) {
                int r0 = (wr1 * 2 + i) * 16 + gid;
                af[i][0] = xs[r0 * XS + kt * 8 + tig];
                af[i][1] = xs[(r0 + 8) * XS + kt * 8 + tig];
                af[i][2] = xs[r0 * XS + kt * 8 + tig + 4];
                af[i][3] = xs[(r0 + 8) * XS + kt * 8 + tig + 4];
            }
            #pragma unroll
            for (int j = 0; j < 4; j++) {
                int nc = (wc1 * 4 + j) * 8 + gid;
                bf[j][0] = rs[(kt * 8 + tig) * DP + nc];
                bf[j][1] = rs[(kt * 8 + tig + 4) * DP + nc];
            }
            #pragma unroll
            for (int i = 0; i < 2; i++)
                #pragma unroll
                for (int j = 0; j < 4; j++)
                    mma8(accT[i][j], af[i], bf[j]);
        }
    }

    // ---- store T (tf32) ----
    #pragma unroll
    for (int i = 0; i < 2; i++)
        #pragma unroll
        for (int j = 0; j < 4; j++) {
            int r0 = (wr1 * 2 + i) * 16 + gid;
            int nc = (wc1 * 4 + j) * 8 + 2 * tig;
            uint2 lo = make_uint2(f2tf(accT[i][j][0]), f2tf(accT[i][j][1]));
            uint2 hi = make_uint2(f2tf(accT[i][j][2]), f2tf(accT[i][j][3]));
            *(uint2*)&ts[r0 * DP + nc]       = lo;
            *(uint2*)&ts[(r0 + 8) * DP + nc] = hi;
        }
    __syncthreads();   // T visible; x chunk (lts alias) free to overwrite

    // ================= GEMM2 =================
    const int m   = w >> 2;           // 4 warps per m-row
    const int sw  = w & 3;
    const int wr2 = sw / WC2, wc2 = sw % WC2;
    float accY[2][4][4];
    #pragma unroll
    for (int i = 0; i < 2; i++)
        #pragma unroll
        for (int j = 0; j < 4; j++)
            #pragma unroll
            for (int q = 0; q < 4; q++) accY[i][j][q] = 0.0f;

    for (int ac = 0; ac < NC2; ac++) {
        if (ac) __syncthreads();   // protect lts overwrite vs previous mma reads
        // ---- LT chunk: [B][32 a], L transposed, /3, tf32, stride LTS ----
        #pragma unroll
        for (int i = tid; i < 32 * B; i += THREADS) {
            int acx = i / B, b = i % B;
            lts[b * LTS + acx] = f2tf(Lg[(ac * 32 + acx) * B + b] * (1.0f / 3.0f));
        }
        __syncthreads();

        #pragma unroll
        for (int kt = 0; kt < 4; kt++) {
            uint32_t af[2][4], bf[4][2];
            #pragma unroll
            for (int i = 0; i < 2; i++) {
                int rb = (wr2 * 2 + i) * 16 + gid;
                af[i][0] = lts[rb * LTS + kt * 8 + tig];
                af[i][1] = lts[(rb + 8) * LTS + kt * 8 + tig];
                af[i][2] = lts[rb * LTS + kt * 8 + tig + 4];
                af[i][3] = lts[(rb + 8) * LTS + kt * 8 + tig + 4];
            }
            #pragma unroll
            for (int j = 0; j < 4; j++) {
                int nc = (wc2 * 4 + j) * 8 + gid;
                bf[j][0] = ts[(m * A + ac * 32 + kt * 8 + tig) * DP + nc];
                bf[j][1] = ts[(m * A + ac * 32 + kt * 8 + tig + 4) * DP + nc];
            }
            #pragma unroll
            for (int i = 0; i < 2; i++)
                #pragma unroll
                for (int j = 0; j < 4; j++)
                    mma8(accY[i][j], af[i], bf[j]);
        }
    }

    // ---- RMW y (swizzled): ownership disjoint per thread within a factor ----
    #pragma unroll
    for (int i = 0; i < 2; i++)
        #pragma unroll
        for (int j = 0; j < 4; j++) {
            int b = (wr2 * 2 + i) * 16 + gid;
            int d = (wc2 * 4 + j) * 8 + 2 * tig;
            int n0 = b * D + d;
            int s0 = n0 + 2 * (n0 >> 5);
            float2 v0 = *(float2*)&ys[m * YS + s0];
            v0.x += accY[i][j][0]; v0.y += accY[i][j][1];
            *(float2*)&ys[m * YS + s0] = v0;
            int n2 = (b + 8) * D + d;
            int s2 = n2 + 2 * (n2 >> 5);
            float2 v2 = *(float2*)&ys[m * YS + s2];
            v2.x += accY[i][j][2]; v2.y += accY[i][j][3];
            *(float2*)&ys[m * YS + s2] = v2;
        }
}

__global__ __launch_bounds__(THREADS, 1) void klinear_kernel(
    const float* __restrict__ x,
    const float* __restrict__ L0, const float* __restrict__ R0,
    const float* __restrict__ L1, const float* __restrict__ R1,
    const float* __restrict__ L2, const float* __restrict__ R2,
    const float* __restrict__ bias,
    float* __restrict__ out)
{
    extern __shared__ float smem[];
    const int tid = threadIdx.x;
    const int m0  = blockIdx.x * MT;

    // zero y accumulator (bias added in epilogue)
    for (int i = tid; i < MT * YS; i += THREADS)
        smem[OFF_Y + i] = 0.0f;
    // (first factor's chunk-top __syncthreads orders this before any use)

    factor< 64,  64,  64,  64>(x, L0, R0, smem, m0, tid);
    factor< 32,  32, 128, 128>(x, L1, R1, smem, m0, tid);
    factor<128, 128,  32,  32>(x, L2, R2, smem, m0, tid);

    __syncthreads();

    // epilogue: y + bias -> out; thread owns n in [8*tid, 8*tid+8)
    const int n0 = tid * 8;
    const int s  = n0 + 2 * (n0 >> 5);   // contiguous within the 8-run
    float4 b0 = *(const float4*)&bias[n0];
    float4 b1 = *(const float4*)&bias[n0 + 4];
    #pragma unroll
    for (int m = 0; m < MT; m++) {
        const float* yr = smem + OFF_Y + m * YS + s;
        float2 p0 = *(const float2*)&yr[0];
        float2 p1 = *(const float2*)&yr[2];
        float2 p2 = *(const float2*)&yr[4];
        float2 p3 = *(const float2*)&yr[6];
        float4 o0 = make_float4(p0.x + b0.x, p0.y + b0.y, p1.x + b0.z, p1.y + b0.w);
        float4 o1 = make_float4(p2.x + b1.x, p2.y + b1.y, p3.x + b1.z, p3.y + b1.w);
        *(float4*)&out[(size_t)(m0 + m) * NF + n0]     = o0;
        *(float4*)&out[(size_t)(m0 + m) * NF + n0 + 4] = o1;
    }
}

extern "C" void kernel_launch(void* const* d_in, const int* in_sizes, int n_in,
                              void* d_out, int out_size)
{
    const float* x    = (const float*)d_in[0];
    const float* L0   = (const float*)d_in[1];
    const float* R0   = (const float*)d_in[2];
    const float* L1   = (const float*)d_in[3];
    const float* R1   = (const float*)d_in[4];
    const float* L2   = (const float*)d_in[5];
    const float* R2   = (const float*)d_in[6];
    const float* bias = (const float*)d_in[7];
    float* out = (float*)d_out;

    static bool attr_set = false;
    if (!attr_set) {
        cudaFuncSetAttribute(klinear_kernel,
                             cudaFuncAttributeMaxDynamicSharedMemorySize, SMEM_BYTES);
        attr_set = true;
    }

    klinear_kernel<<<16384 / MT, THREADS, SMEM_BYTES>>>(
        x, L0, R0, L1, R1, L2, R2, bias, out);
}